// round 12
// baseline (speedup 1.0000x reference)
#include <cuda_runtime.h>
#include <math.h>
#include <stdint.h>

#define S_LEN 2048
#define B_SZ  64
#define XDIM  64
#define HDIM  256
#define ODIM  64

// Scratch (alloc-free rule: __device__ globals)
__device__ float g_U[S_LEN * B_SZ * HDIM];   // U[t,b,:] = feat @ Wih^T + bih + bhh
__device__ float g_Hs[S_LEN * B_SZ * HDIM];  // hidden state ENTERING step t (h_0 = 0)

// ------------------------- packed fp32x2 helpers ---------------------------
__device__ __forceinline__ unsigned long long fma2(unsigned long long a,
                                                   unsigned long long b,
                                                   unsigned long long c) {
    unsigned long long d;
    asm("fma.rn.f32x2 %0, %1, %2, %3;" : "=l"(d) : "l"(a), "l"(b), "l"(c));
    return d;
}
__device__ __forceinline__ unsigned long long add2(unsigned long long a,
                                                   unsigned long long b) {
    unsigned long long d;
    asm("add.rn.f32x2 %0, %1, %2;" : "=l"(d) : "l"(a), "l"(b));
    return d;
}
__device__ __forceinline__ float pk_lo(unsigned long long v) {
    return __uint_as_float((unsigned)(v & 0xffffffffull));
}
__device__ __forceinline__ float pk_hi(unsigned long long v) {
    return __uint_as_float((unsigned)(v >> 32));
}
// splat one fp32 into both lanes of a packed f32x2
__device__ __forceinline__ unsigned long long pk2(float v) {
    unsigned long long d;
    unsigned u = __float_as_uint(v);
    asm("mov.b64 %0, {%1, %2};" : "=l"(d) : "r"(u), "r"(u));
    return d;
}

// ---------------------------------------------------------------------------
// Kernel A v2 (R10): feat = tanh(x @ Wx + bx); U = feat @ Wih^T + (bih + bhh)
// ---------------------------------------------------------------------------
__global__ __launch_bounds__(256, 1) void kA(
    const float* __restrict__ x,
    const float* __restrict__ Wx, const float* __restrict__ bx,
    const float* __restrict__ Wih, const float* __restrict__ bih,
    const float* __restrict__ bhh)
{
    extern __shared__ float sm[];
    float* sWx   = sm;                    // [64][128]
    float* sWihT = sWx + 64 * 128;        // [128][260]
    float* sbx   = sWihT + 128 * 260;     // [128]
    float* sbU   = sbx + 128;             // [256]
    float* sx    = sbU + 256;             // [32][64]
    float* sfeat = sx + 32 * 64;          // [32][128]

    const int t = threadIdx.x;

    for (int idx = t; idx < 64 * 128; idx += 256) sWx[idx] = Wx[idx];
    for (int idx = t; idx < 256 * 128; idx += 256) {
        int i = idx >> 7, j = idx & 127;
        sWihT[j * 260 + i] = Wih[idx];
    }
    if (t < 128) sbx[t] = bx[t];
    sbU[t] = bih[t] + bhh[t];
    __syncthreads();

    const int rg = t >> 6;          // 0..3 -> rows rg*8 + q
    const int c2 = t & 63;          // phase1 col pair {2c2, 2c2+1}
    const int ii = c2 * 4;          // phase2: 4 consecutive outputs
    const int ntiles = (S_LEN * B_SZ) / 32;

    for (int tile = blockIdx.x; tile < ntiles; tile += gridDim.x) {
        const int row0 = tile * 32;
        { // load 32x64 x tile (contiguous 8KB = 512 float4)
            const float4* src = (const float4*)(x + (size_t)row0 * XDIM);
            ((float4*)sx)[t]       = src[t];
            ((float4*)sx)[t + 256] = src[t + 256];
        }
        __syncthreads();

        // phase 1: feat = tanh(x @ Wx + bx)   (packed f32x2, 8 rows/thread)
        unsigned long long a[8];
        #pragma unroll
        for (int q = 0; q < 8; q++) a[q] = 0ull;
        #pragma unroll 2
        for (int k4 = 0; k4 < 64; k4 += 4) {
            float xv[8][4];
            #pragma unroll
            for (int q = 0; q < 8; q++)
                *(float4*)&xv[q][0] = *(const float4*)&sx[(rg * 8 + q) * 64 + k4];
            #pragma unroll
            for (int s = 0; s < 4; s++) {
                unsigned long long w =
                    *(const unsigned long long*)&sWx[(k4 + s) * 128 + 2 * c2];
                #pragma unroll
                for (int q = 0; q < 8; q++)
                    a[q] = fma2(pk2(xv[q][s]), w, a[q]);
            }
        }
        {
            const float bx0 = sbx[2 * c2], bx1 = sbx[2 * c2 + 1];
            #pragma unroll
            for (int q = 0; q < 8; q++) {
                const int row = rg * 8 + q;
                sfeat[row * 128 + 2 * c2]     = tanhf(pk_lo(a[q]) + bx0);
                sfeat[row * 128 + 2 * c2 + 1] = tanhf(pk_hi(a[q]) + bx1);
            }
        }
        __syncthreads();

        // phase 2: U = feat @ Wih^T + bias   (packed f32x2, 8 rows/thread)
        unsigned long long acc01[8], acc23[8];
        #pragma unroll
        for (int q = 0; q < 8; q++) { acc01[q] = 0ull; acc23[q] = 0ull; }
        #pragma unroll 2
        for (int j4 = 0; j4 < 128; j4 += 4) {
            float f[8][4];
            #pragma unroll
            for (int q = 0; q < 8; q++)
                *(float4*)&f[q][0] = *(const float4*)&sfeat[(rg * 8 + q) * 128 + j4];
            #pragma unroll
            for (int s = 0; s < 4; s++) {
                ulonglong2 w = *(const ulonglong2*)&sWihT[(j4 + s) * 260 + ii];
                #pragma unroll
                for (int q = 0; q < 8; q++) {
                    unsigned long long fs = pk2(f[q][s]);
                    acc01[q] = fma2(fs, w.x, acc01[q]);
                    acc23[q] = fma2(fs, w.y, acc23[q]);
                }
            }
        }
        float4 bU = *(const float4*)&sbU[ii];
        #pragma unroll
        for (int q = 0; q < 8; q++) {
            float4 o;
            o.x = pk_lo(acc01[q]) + bU.x; o.y = pk_hi(acc01[q]) + bU.y;
            o.z = pk_lo(acc23[q]) + bU.z; o.w = pk_hi(acc23[q]) + bU.w;
            *((float4*)&g_U[(size_t)(row0 + rg * 8 + q) * HDIM + ii]) = o;
        }
        __syncthreads();
    }
}

// ---------------------------------------------------------------------------
// Kernel B v11: sequential recurrence, ONE plain CTA per batch element,
// ALL 256 Whh weights per output row held in REGISTERS (64 ulonglong2 =
// 128 regs/thread; 256 thr/CTA -> 256-reg budget, ~170 used, no spill).
// Zero weight smem -> crossbar traffic is ONLY the 512 broadcast-wf of h
// per step (the irreducible floor), overlapping the 512-cyc FFMA2 issue
// floor. No clusters, no mbarriers; one __syncthreads per step; h double-
// buffered; two-step-ahead g_U prefetch. Accumulator interleave identical
// to v6 (rel_err 4.065e-07 measured there).
// ---------------------------------------------------------------------------
__global__ __launch_bounds__(256, 1) void kB(
    const float* __restrict__ Whh,
    const float* __restrict__ sigmas)
{
    __shared__ __align__(16) float sh[2][256];   // double-buffered h

    const int tid = threadIdx.x;          // output index i
    const int b   = blockIdx.x;           // batch element

    // full weight row in registers: W[tid][0..256) as 64 ulonglong2
    ulonglong2 wreg[64];
    {
        const ulonglong2* ws = (const ulonglong2*)(Whh + (size_t)tid * HDIM);
        #pragma unroll
        for (int i = 0; i < 64; i++) wreg[i] = ws[i];
    }

    const float alpha = 1.0f / (1.0f + expf(-sigmas[tid & 3]));
    const float oma   = 1.0f - alpha;

    sh[0][tid] = 0.f;
    sh[1][tid] = 0.f;
    __syncthreads();

    float h_reg = 0.f;
    // two-step-ahead u pipeline
    float u0 = g_U[(size_t)b * HDIM + tid];                 // step 0
    float u1 = g_U[((size_t)B_SZ + b) * HDIM + tid];        // step 1
    int cur = 0;

    for (int t = 0; t < S_LEN; t++) {
        const float u = u0;
        u0 = u1;
        if (t + 2 < S_LEN)
            u1 = g_U[((size_t)(t + 2) * B_SZ + b) * HDIM + tid];

        g_Hs[((size_t)t * B_SZ + b) * HDIM + tid] = h_reg;  // state entering t

        const float* hc = sh[cur];

        unsigned long long a0 = 0ull, a1 = 0ull, a2 = 0ull, a3 = 0ull;
        #pragma unroll
        for (int i = 0; i < 64; i += 2) {
            ulonglong2 h0 = *(const ulonglong2*)&hc[i * 4];
            a0 = fma2(wreg[i].x, h0.x, a0);
            a1 = fma2(wreg[i].y, h0.y, a1);
            ulonglong2 h1 = *(const ulonglong2*)&hc[i * 4 + 4];
            a2 = fma2(wreg[i + 1].x, h1.x, a2);
            a3 = fma2(wreg[i + 1].y, h1.y, a3);
        }
        unsigned long long c = add2(add2(a0, a1), add2(a2, a3));
        const float s  = pk_lo(c) + pk_hi(c) + u;

        const float hn = tanhf(s);
        h_reg = oma * h_reg + alpha * hn;

        sh[cur ^ 1][tid] = h_reg;            // publish for step t+1
        cur ^= 1;
        __syncthreads();
    }
}

// ---------------------------------------------------------------------------
// Kernel C v2 (R10): z = tanh(h @ Whx + bhx); y = z @ Wout + bout
// ---------------------------------------------------------------------------
__global__ __launch_bounds__(256, 1) void kC(
    const float* __restrict__ Whx, const float* __restrict__ bhx,
    const float* __restrict__ Wout, const float* __restrict__ bout,
    float* __restrict__ y)
{
    extern __shared__ float sm[];
    float* sWhx  = sm;                   // [256][128]
    float* sWout = sWhx + 256 * 128;     // [128][64]
    float* sbhx  = sWout + 128 * 64;     // [128]
    float* sbout = sbhx + 128;           // [64]
    float* sht   = sbout + 64;           // [32][256]
    float* sz    = sht + 32 * 256;       // [32][128]

    const int t = threadIdx.x;
    for (int idx = t; idx < 256 * 128; idx += 256) sWhx[idx] = Whx[idx];
    for (int idx = t; idx < 128 * 64; idx += 256) sWout[idx] = Wout[idx];
    if (t < 128) sbhx[t] = bhx[t];
    if (t < 64)  sbout[t] = bout[t];
    __syncthreads();

    const int rg  = t >> 5;          // 0..7 -> rows rg*4 + q   (phase1)
    const int jj4 = (t & 31) * 4;    // phase1: 4 consecutive z cols
    const int rr  = t >> 4;          // 0..15 -> rows rr*2 + q2 (phase2)
    const int oo4 = (t & 15) * 4;    // phase2: 4 consecutive outputs
    const int ntiles = (S_LEN * B_SZ) / 32;

    for (int tile = blockIdx.x; tile < ntiles; tile += gridDim.x) {
        const int row0 = tile * 32;
        { // load 32x256 hidden-state tile (contiguous 32KB = 2048 float4)
            const float4* src = (const float4*)(g_Hs + (size_t)row0 * HDIM);
            float4* dst = (float4*)sht;
            #pragma unroll
            for (int q = 0; q < 8; q++) dst[q * 256 + t] = src[q * 256 + t];
        }
        __syncthreads();

        // phase 1: z = tanh(h @ Whx + bhx)   (packed f32x2, 4 rows/thread)
        unsigned long long acc01[4], acc23[4];
        #pragma unroll
        for (int q = 0; q < 4; q++) { acc01[q] = 0ull; acc23[q] = 0ull; }
        #pragma unroll 2
        for (int i4 = 0; i4 < 256; i4 += 4) {
            float hq[4][4];
            #pragma unroll
            for (int q = 0; q < 4; q++)
                *(float4*)&hq[q][0] = *(const float4*)&sht[(rg * 4 + q) * 256 + i4];
            #pragma unroll
            for (int s = 0; s < 4; s++) {
                ulonglong2 w = *(const ulonglong2*)&sWhx[(i4 + s) * 128 + jj4];
                #pragma unroll
                for (int q = 0; q < 4; q++) {
                    unsigned long long hs = pk2(hq[q][s]);
                    acc01[q] = fma2(hs, w.x, acc01[q]);
                    acc23[q] = fma2(hs, w.y, acc23[q]);
                }
            }
        }
        float4 bz = *(const float4*)&sbhx[jj4];
        #pragma unroll
        for (int q = 0; q < 4; q++) {
            const int rw = rg * 4 + q;
            sz[rw * 128 + jj4 + 0] = tanhf(pk_lo(acc01[q]) + bz.x);
            sz[rw * 128 + jj4 + 1] = tanhf(pk_hi(acc01[q]) + bz.y);
            sz[rw * 128 + jj4 + 2] = tanhf(pk_lo(acc23[q]) + bz.z);
            sz[rw * 128 + jj4 + 3] = tanhf(pk_hi(acc23[q]) + bz.w);
        }
        __syncthreads();

        // phase 2: y = z @ Wout + bout   (2 rows/thread)
        float4 o[2];
        o[0] = make_float4(0.f, 0.f, 0.f, 0.f);
        o[1] = make_float4(0.f, 0.f, 0.f, 0.f);
        #pragma unroll 2
        for (int j4 = 0; j4 < 128; j4 += 4) {
            float zq[2][4];
            #pragma unroll
            for (int q2 = 0; q2 < 2; q2++)
                *(float4*)&zq[q2][0] = *(const float4*)&sz[(rr * 2 + q2) * 128 + j4];
            #pragma unroll
            for (int s = 0; s < 4; s++) {
                float4 w = *(const float4*)&sWout[(j4 + s) * 64 + oo4];
                #pragma unroll
                for (int q2 = 0; q2 < 2; q2++) {
                    o[q2].x = fmaf(zq[q2][s], w.x, o[q2].x);
                    o[q2].y = fmaf(zq[q2][s], w.y, o[q2].y);
                    o[q2].z = fmaf(zq[q2][s], w.z, o[q2].z);
                    o[q2].w = fmaf(zq[q2][s], w.w, o[q2].w);
                }
            }
        }
        float4 bo = *(const float4*)&sbout[oo4];
        #pragma unroll
        for (int q2 = 0; q2 < 2; q2++) {
            float4 ov;
            ov.x = o[q2].x + bo.x; ov.y = o[q2].y + bo.y;
            ov.z = o[q2].z + bo.z; ov.w = o[q2].w + bo.w;
            *((float4*)&y[(size_t)(row0 + rr * 2 + q2) * ODIM + oo4]) = ov;
        }
        __syncthreads();
    }
}

// ---------------------------------------------------------------------------
extern "C" void kernel_launch(void* const* d_in, const int* in_sizes, int n_in,
                              void* d_out, int out_size)
{
    const float* x      = (const float*)d_in[0];
    const float* Wx     = (const float*)d_in[1];
    const float* bx     = (const float*)d_in[2];
    const float* Wih    = (const float*)d_in[3];
    const float* bih    = (const float*)d_in[4];
    const float* Whh    = (const float*)d_in[5];
    const float* bhh    = (const float*)d_in[6];
    const float* Whx    = (const float*)d_in[7];
    const float* bhx    = (const float*)d_in[8];
    const float* Wout   = (const float*)d_in[9];
    const float* bout   = (const float*)d_in[10];
    const float* sigmas = (const float*)d_in[11];
    float* y = (float*)d_out;

    const size_t smA = (size_t)(64*128 + 128*260 + 128 + 256 + 32*64 + 32*128) * 4;
    const size_t smC = (size_t)(256*128 + 128*64 + 128 + 64 + 32*256 + 32*128) * 4;

    cudaFuncSetAttribute(kA, cudaFuncAttributeMaxDynamicSharedMemorySize, (int)smA);
    cudaFuncSetAttribute(kC, cudaFuncAttributeMaxDynamicSharedMemorySize, (int)smC);

    kA<<<148, 256, smA>>>(x, Wx, bx, Wih, bih, bhh);
    kB<<<64, 256>>>(Whh, sigmas);
    kC<<<148, 256, smC>>>(Whx, bhx, Wout, bout, y);
}

// round 13
// speedup vs baseline: 2.3563x; 2.3563x over previous
#include <cuda_runtime.h>
#include <math.h>
#include <stdint.h>

#define S_LEN 2048
#define B_SZ  64
#define XDIM  64
#define HDIM  256
#define ODIM  64

// Scratch (alloc-free rule: __device__ globals)
__device__ float g_U[S_LEN * B_SZ * HDIM];   // U[t,b,:] = feat @ Wih^T + bih + bhh
__device__ float g_Hs[S_LEN * B_SZ * HDIM];  // hidden state ENTERING step t (h_0 = 0)

// ------------------------- packed fp32x2 helpers ---------------------------
__device__ __forceinline__ unsigned long long fma2(unsigned long long a,
                                                   unsigned long long b,
                                                   unsigned long long c) {
    unsigned long long d;
    asm("fma.rn.f32x2 %0, %1, %2, %3;" : "=l"(d) : "l"(a), "l"(b), "l"(c));
    return d;
}
__device__ __forceinline__ unsigned long long add2(unsigned long long a,
                                                   unsigned long long b) {
    unsigned long long d;
    asm("add.rn.f32x2 %0, %1, %2;" : "=l"(d) : "l"(a), "l"(b));
    return d;
}
__device__ __forceinline__ float pk_lo(unsigned long long v) {
    return __uint_as_float((unsigned)(v & 0xffffffffull));
}
__device__ __forceinline__ float pk_hi(unsigned long long v) {
    return __uint_as_float((unsigned)(v >> 32));
}
// splat one fp32 into both lanes of a packed f32x2
__device__ __forceinline__ unsigned long long pk2(float v) {
    unsigned long long d;
    unsigned u = __float_as_uint(v);
    asm("mov.b64 %0, {%1, %2};" : "=l"(d) : "r"(u), "r"(u));
    return d;
}
// pack two distinct fp32 into one b64
__device__ __forceinline__ unsigned long long pk2pair(float lo, float hi) {
    unsigned long long d;
    asm("mov.b64 %0, {%1, %2};" : "=l"(d) : "r"(__float_as_uint(lo)),
                                            "r"(__float_as_uint(hi)));
    return d;
}

__device__ __forceinline__ uint32_t smem_u32(const void* p) {
    uint32_t a;
    asm("{ .reg .u64 t; cvta.to.shared.u64 t, %1; cvt.u32.u64 %0, t; }"
        : "=r"(a) : "l"(p));
    return a;
}
__device__ __forceinline__ uint32_t ctarank() {
    uint32_t r;
    asm("mov.u32 %0, %%cluster_ctarank;" : "=r"(r));
    return r;
}
__device__ __forceinline__ uint32_t mapa_peer(uint32_t addr, uint32_t peer) {
    uint32_t r;
    asm("mapa.shared::cluster.u32 %0, %1, %2;" : "=r"(r) : "r"(addr), "r"(peer));
    return r;
}
// remote async 8-byte store with tx-completion on the (pre-mapped) peer mbar
__device__ __forceinline__ void st_async_b64(uint32_t rdaddr, uint32_t rmbaddr,
                                             unsigned long long v) {
    asm volatile(
        "st.async.shared::cluster.mbarrier::complete_tx::bytes.b64 [%0], %1, [%2];"
        :: "r"(rdaddr), "l"(v), "r"(rmbaddr) : "memory");
}
__device__ __forceinline__ void mbar_init(uint32_t addr, uint32_t cnt) {
    asm volatile("mbarrier.init.shared.b64 [%0], %1;" :: "r"(addr), "r"(cnt) : "memory");
}
__device__ __forceinline__ void mbar_expect_tx(uint32_t addr, uint32_t bytes) {
    asm volatile("mbarrier.arrive.expect_tx.shared.b64 _, [%0], %1;"
                 :: "r"(addr), "r"(bytes) : "memory");
}
__device__ __forceinline__ void mbar_wait_cta(uint32_t addr, uint32_t parity) {
    asm volatile(
        "{\n\t.reg .pred P;\n\t"
        "W_%=:\n\t"
        "mbarrier.try_wait.parity.acquire.cta.shared::cta.b64 P, [%0], %1, 0x989680;\n\t"
        "@!P bra W_%=;\n\t}"
        :: "r"(addr), "r"(parity) : "memory");
}

// ---------------------------------------------------------------------------
// Kernel A v2 (R10): feat = tanh(x @ Wx + bx); U = feat @ Wih^T + (bih + bhh)
// ---------------------------------------------------------------------------
__global__ __launch_bounds__(256, 1) void kA(
    const float* __restrict__ x,
    const float* __restrict__ Wx, const float* __restrict__ bx,
    const float* __restrict__ Wih, const float* __restrict__ bih,
    const float* __restrict__ bhh)
{
    extern __shared__ float sm[];
    float* sWx   = sm;                    // [64][128]
    float* sWihT = sWx + 64 * 128;        // [128][260]
    float* sbx   = sWihT + 128 * 260;     // [128]
    float* sbU   = sbx + 128;             // [256]
    float* sx    = sbU + 256;             // [32][64]
    float* sfeat = sx + 32 * 64;          // [32][128]

    const int t = threadIdx.x;

    for (int idx = t; idx < 64 * 128; idx += 256) sWx[idx] = Wx[idx];
    for (int idx = t; idx < 256 * 128; idx += 256) {
        int i = idx >> 7, j = idx & 127;
        sWihT[j * 260 + i] = Wih[idx];
    }
    if (t < 128) sbx[t] = bx[t];
    sbU[t] = bih[t] + bhh[t];
    __syncthreads();

    const int rg = t >> 6;          // 0..3 -> rows rg*8 + q
    const int c2 = t & 63;          // phase1 col pair {2c2, 2c2+1}
    const int ii = c2 * 4;          // phase2: 4 consecutive outputs
    const int ntiles = (S_LEN * B_SZ) / 32;

    for (int tile = blockIdx.x; tile < ntiles; tile += gridDim.x) {
        const int row0 = tile * 32;
        { // load 32x64 x tile (contiguous 8KB = 512 float4)
            const float4* src = (const float4*)(x + (size_t)row0 * XDIM);
            ((float4*)sx)[t]       = src[t];
            ((float4*)sx)[t + 256] = src[t + 256];
        }
        __syncthreads();

        // phase 1: feat = tanh(x @ Wx + bx)   (packed f32x2, 8 rows/thread)
        unsigned long long a[8];
        #pragma unroll
        for (int q = 0; q < 8; q++) a[q] = 0ull;
        #pragma unroll 2
        for (int k4 = 0; k4 < 64; k4 += 4) {
            float xv[8][4];
            #pragma unroll
            for (int q = 0; q < 8; q++)
                *(float4*)&xv[q][0] = *(const float4*)&sx[(rg * 8 + q) * 64 + k4];
            #pragma unroll
            for (int s = 0; s < 4; s++) {
                unsigned long long w =
                    *(const unsigned long long*)&sWx[(k4 + s) * 128 + 2 * c2];
                #pragma unroll
                for (int q = 0; q < 8; q++)
                    a[q] = fma2(pk2(xv[q][s]), w, a[q]);
            }
        }
        {
            const float bx0 = sbx[2 * c2], bx1 = sbx[2 * c2 + 1];
            #pragma unroll
            for (int q = 0; q < 8; q++) {
                const int row = rg * 8 + q;
                sfeat[row * 128 + 2 * c2]     = tanhf(pk_lo(a[q]) + bx0);
                sfeat[row * 128 + 2 * c2 + 1] = tanhf(pk_hi(a[q]) + bx1);
            }
        }
        __syncthreads();

        // phase 2: U = feat @ Wih^T + bias   (packed f32x2, 8 rows/thread)
        unsigned long long acc01[8], acc23[8];
        #pragma unroll
        for (int q = 0; q < 8; q++) { acc01[q] = 0ull; acc23[q] = 0ull; }
        #pragma unroll 2
        for (int j4 = 0; j4 < 128; j4 += 4) {
            float f[8][4];
            #pragma unroll
            for (int q = 0; q < 8; q++)
                *(float4*)&f[q][0] = *(const float4*)&sfeat[(rg * 8 + q) * 128 + j4];
            #pragma unroll
            for (int s = 0; s < 4; s++) {
                ulonglong2 w = *(const ulonglong2*)&sWihT[(j4 + s) * 260 + ii];
                #pragma unroll
                for (int q = 0; q < 8; q++) {
                    unsigned long long fs = pk2(f[q][s]);
                    acc01[q] = fma2(fs, w.x, acc01[q]);
                    acc23[q] = fma2(fs, w.y, acc23[q]);
                }
            }
        }
        float4 bU = *(const float4*)&sbU[ii];
        #pragma unroll
        for (int q = 0; q < 8; q++) {
            float4 o;
            o.x = pk_lo(acc01[q]) + bU.x; o.y = pk_hi(acc01[q]) + bU.y;
            o.z = pk_lo(acc23[q]) + bU.z; o.w = pk_hi(acc23[q]) + bU.w;
            *((float4*)&g_U[(size_t)(row0 + rg * 8 + q) * HDIM + ii]) = o;
        }
        __syncthreads();
    }
}

// ---------------------------------------------------------------------------
// Kernel B v12: R4/R10 winner structure, with the cross-CTA publish packed
// into 64 x 8-byte st.async.b64 (was 128 x 4B) via one finalizer-warp shfl,
// and mapa address computation hoisted out of the loop. Everything else —
// buffers, parities, syncs, dot order — identical to kB v4.
// ---------------------------------------------------------------------------
__global__ __launch_bounds__(256, 1) __cluster_dims__(2, 1, 1)
void kB(const float* __restrict__ Whh, const float* __restrict__ sigmas)
{
    __shared__ __align__(16) float sh[2][256];  // double-buffered h vector
    __shared__ __align__(16) float spart[128];  // intra-CTA partial exchange
    __shared__ __align__(8)  unsigned long long mbar[2];

    const int tid   = threadIdx.x;
    const int i_loc = tid & 127;
    const int half  = tid >> 7;
    const uint32_t rank = ctarank();
    const uint32_t peer = rank ^ 1u;
    const int r  = (int)rank;
    const int b  = blockIdx.x >> 1;
    const int gi = r * 128 + i_loc;          // output index this thread serves
    const bool fresh     = (half == r);      // my K-half is produced locally
    const bool finalizer = (half == 0);
    const int waiter_leader = (r == 0) ? 128 : 0;   // one mbar-waiting thread

    // weights: W[gi][128*half + kk], kk in [0,128) -> 32 ulonglong2 = 128 regs
    ulonglong2 wreg[32];
    {
        const ulonglong2* ws =
            (const ulonglong2*)(Whh + (size_t)gi * HDIM + 128 * half);
        #pragma unroll
        for (int i = 0; i < 32; i++) wreg[i] = ws[i];
    }

    const float alpha = 1.0f / (1.0f + expf(-sigmas[gi & 3]));
    const float oma   = 1.0f - alpha;

    sh[0][tid] = 0.f;
    sh[1][tid] = 0.f;
    const uint32_t mb[2] = { smem_u32(&mbar[0]), smem_u32(&mbar[1]) };
    const uint32_t sh_a  = smem_u32(&sh[0][0]);
    if (tid == 0) { mbar_init(mb[0], 1); mbar_init(mb[1], 1); }
    __syncthreads();
    if (tid == waiter_leader) {              // cover sends of steps 0 and 1
        mbar_expect_tx(mb[0], 512);
        mbar_expect_tx(mb[1], 512);
    }
    __syncthreads();
    asm volatile("barrier.cluster.arrive.aligned;" ::: "memory");
    asm volatile("barrier.cluster.wait.aligned;" ::: "memory");

    // precomputed remote addresses (even finalizer lanes only use these):
    // data dst covers sh[wb][gi..gi+1]; mbar dst is the peer's mb[wb]
    uint32_t rdA[2], rmbA[2];
    {
        rdA[0]  = mapa_peer(sh_a + (uint32_t)((0 * 256 + gi) * 4), peer);
        rdA[1]  = mapa_peer(sh_a + (uint32_t)((1 * 256 + gi) * 4), peer);
        rmbA[0] = mapa_peer(mb[0], peer);
        rmbA[1] = mapa_peer(mb[1], peer);
    }

    float h_reg  = 0.f;                      // finalizer-owned h[gi]
    float u_next = finalizer ? g_U[(size_t)b * HDIM + gi] : 0.f;

    for (int t = 0; t < S_LEN; t++) {
        // h entering step t lives in buffer (t-1)&1 == (t+1)&1
        const float* hsrc = sh[(t + 1) & 1] + 128 * half;

        // threads on the remote K-half wait for the peer's step-(t-1) h values
        if (!fresh && t > 0) {
            const int pm = (t - 1) & 1;
            mbar_wait_cta(mb[pm], (uint32_t)(((t - 1) >> 1) & 1));
            if (tid == waiter_leader)        // re-arm for use at step t+1
                mbar_expect_tx(mb[pm], 512);
        }

        // partial = sum_kk W[gi][128*half+kk] * h[128*half+kk]
        unsigned long long a0 = 0ull, a1 = 0ull, a2 = 0ull, a3 = 0ull;
        #pragma unroll
        for (int i = 0; i < 32; i += 2) {
            ulonglong2 h0 = *(const ulonglong2*)&hsrc[i * 4];
            a0 = fma2(wreg[i].x, h0.x, a0);
            a1 = fma2(wreg[i].y, h0.y, a1);
            ulonglong2 h1 = *(const ulonglong2*)&hsrc[i * 4 + 4];
            a2 = fma2(wreg[i + 1].x, h1.x, a2);
            a3 = fma2(wreg[i + 1].y, h1.y, a3);
        }
        unsigned long long c = add2(add2(a0, a1), add2(a2, a3));
        const float partial = pk_lo(c) + pk_hi(c);

        if (!finalizer) spart[i_loc] = partial;
        __syncthreads();

        if (finalizer) {
            const float u = u_next;
            if (t + 1 < S_LEN)
                u_next = g_U[((size_t)(t + 1) * B_SZ + b) * HDIM + gi];
            g_Hs[((size_t)t * B_SZ + b) * HDIM + gi] = h_reg;  // state entering t

            const float s  = partial + spart[i_loc] + u;
            const float hn = tanhf(s);
            h_reg = oma * h_reg + alpha * hn;

            const int wb = t & 1;
            sh[wb][gi] = h_reg;                               // local publish

            // pair-packed remote publish: even lanes send (h[gi], h[gi+1])
            const float h_hi = __shfl_down_sync(0xffffffffu, h_reg, 1);
            if ((tid & 1) == 0)
                st_async_b64(rdA[wb], rmbA[wb], pk2pair(h_reg, h_hi));
        }
        __syncthreads();
    }

    asm volatile("barrier.cluster.arrive.aligned;" ::: "memory");
    asm volatile("barrier.cluster.wait.aligned;" ::: "memory");
}

// ---------------------------------------------------------------------------
// Kernel C v2 (R10): z = tanh(h @ Whx + bhx); y = z @ Wout + bout
// ---------------------------------------------------------------------------
__global__ __launch_bounds__(256, 1) void kC(
    const float* __restrict__ Whx, const float* __restrict__ bhx,
    const float* __restrict__ Wout, const float* __restrict__ bout,
    float* __restrict__ y)
{
    extern __shared__ float sm[];
    float* sWhx  = sm;                   // [256][128]
    float* sWout = sWhx + 256 * 128;     // [128][64]
    float* sbhx  = sWout + 128 * 64;     // [128]
    float* sbout = sbhx + 128;           // [64]
    float* sht   = sbout + 64;           // [32][256]
    float* sz    = sht + 32 * 256;       // [32][128]

    const int t = threadIdx.x;
    for (int idx = t; idx < 256 * 128; idx += 256) sWhx[idx] = Whx[idx];
    for (int idx = t; idx < 128 * 64; idx += 256) sWout[idx] = Wout[idx];
    if (t < 128) sbhx[t] = bhx[t];
    if (t < 64)  sbout[t] = bout[t];
    __syncthreads();

    const int rg  = t >> 5;          // 0..7 -> rows rg*4 + q   (phase1)
    const int jj4 = (t & 31) * 4;    // phase1: 4 consecutive z cols
    const int rr  = t >> 4;          // 0..15 -> rows rr*2 + q2 (phase2)
    const int oo4 = (t & 15) * 4;    // phase2: 4 consecutive outputs
    const int ntiles = (S_LEN * B_SZ) / 32;

    for (int tile = blockIdx.x; tile < ntiles; tile += gridDim.x) {
        const int row0 = tile * 32;
        { // load 32x256 hidden-state tile (contiguous 32KB = 2048 float4)
            const float4* src = (const float4*)(g_Hs + (size_t)row0 * HDIM);
            float4* dst = (float4*)sht;
            #pragma unroll
            for (int q = 0; q < 8; q++) dst[q * 256 + t] = src[q * 256 + t];
        }
        __syncthreads();

        // phase 1: z = tanh(h @ Whx + bhx)   (packed f32x2, 4 rows/thread)
        unsigned long long acc01[4], acc23[4];
        #pragma unroll
        for (int q = 0; q < 4; q++) { acc01[q] = 0ull; acc23[q] = 0ull; }
        #pragma unroll 2
        for (int i4 = 0; i4 < 256; i4 += 4) {
            float hq[4][4];
            #pragma unroll
            for (int q = 0; q < 4; q++)
                *(float4*)&hq[q][0] = *(const float4*)&sht[(rg * 4 + q) * 256 + i4];
            #pragma unroll
            for (int s = 0; s < 4; s++) {
                ulonglong2 w = *(const ulonglong2*)&sWhx[(i4 + s) * 128 + jj4];
                #pragma unroll
                for (int q = 0; q < 4; q++) {
                    unsigned long long hs = pk2(hq[q][s]);
                    acc01[q] = fma2(hs, w.x, acc01[q]);
                    acc23[q] = fma2(hs, w.y, acc23[q]);
                }
            }
        }
        float4 bz = *(const float4*)&sbhx[jj4];
        #pragma unroll
        for (int q = 0; q < 4; q++) {
            const int rw = rg * 4 + q;
            sz[rw * 128 + jj4 + 0] = tanhf(pk_lo(acc01[q]) + bz.x);
            sz[rw * 128 + jj4 + 1] = tanhf(pk_hi(acc01[q]) + bz.y);
            sz[rw * 128 + jj4 + 2] = tanhf(pk_lo(acc23[q]) + bz.z);
            sz[rw * 128 + jj4 + 3] = tanhf(pk_hi(acc23[q]) + bz.w);
        }
        __syncthreads();

        // phase 2: y = z @ Wout + bout   (2 rows/thread)
        float4 o[2];
        o[0] = make_float4(0.f, 0.f, 0.f, 0.f);
        o[1] = make_float4(0.f, 0.f, 0.f, 0.f);
        #pragma unroll 2
        for (int j4 = 0; j4 < 128; j4 += 4) {
            float zq[2][4];
            #pragma unroll
            for (int q2 = 0; q2 < 2; q2++)
                *(float4*)&zq[q2][0] = *(const float4*)&sz[(rr * 2 + q2) * 128 + j4];
            #pragma unroll
            for (int s = 0; s < 4; s++) {
                float4 w = *(const float4*)&sWout[(j4 + s) * 64 + oo4];
                #pragma unroll
                for (int q2 = 0; q2 < 2; q2++) {
                    o[q2].x = fmaf(zq[q2][s], w.x, o[q2].x);
                    o[q2].y = fmaf(zq[q2][s], w.y, o[q2].y);
                    o[q2].z = fmaf(zq[q2][s], w.z, o[q2].z);
                    o[q2].w = fmaf(zq[q2][s], w.w, o[q2].w);
                }
            }
        }
        float4 bo = *(const float4*)&sbout[oo4];
        #pragma unroll
        for (int q2 = 0; q2 < 2; q2++) {
            float4 ov;
            ov.x = o[q2].x + bo.x; ov.y = o[q2].y + bo.y;
            ov.z = o[q2].z + bo.z; ov.w = o[q2].w + bo.w;
            *((float4*)&y[(size_t)(row0 + rr * 2 + q2) * ODIM + oo4]) = ov;
        }
        __syncthreads();
    }
}

// ---------------------------------------------------------------------------
extern "C" void kernel_launch(void* const* d_in, const int* in_sizes, int n_in,
                              void* d_out, int out_size)
{
    const float* x      = (const float*)d_in[0];
    const float* Wx     = (const float*)d_in[1];
    const float* bx     = (const float*)d_in[2];
    const float* Wih    = (const float*)d_in[3];
    const float* bih    = (const float*)d_in[4];
    const float* Whh    = (const float*)d_in[5];
    const float* bhh    = (const float*)d_in[6];
    const float* Whx    = (const float*)d_in[7];
    const float* bhx    = (const float*)d_in[8];
    const float* Wout   = (const float*)d_in[9];
    const float* bout   = (const float*)d_in[10];
    const float* sigmas = (const float*)d_in[11];
    float* y = (float*)d_out;

    const size_t smA = (size_t)(64*128 + 128*260 + 128 + 256 + 32*64 + 32*128) * 4;
    const size_t smC = (size_t)(256*128 + 128*64 + 128 + 64 + 32*256 + 32*128) * 4;

    cudaFuncSetAttribute(kA, cudaFuncAttributeMaxDynamicSharedMemorySize, (int)smA);
    cudaFuncSetAttribute(kC, cudaFuncAttributeMaxDynamicSharedMemorySize, (int)smC);

    kA<<<148, 256, smA>>>(x, Wx, bx, Wih, bih, bhh);
    kB<<<128, 256>>>(Whh, sigmas);
    kC<<<148, 256, smC>>>(Whx, bhx, Wout, bout, y);
}

// round 14
// speedup vs baseline: 2.5936x; 1.1007x over previous
#include <cuda_runtime.h>
#include <math.h>
#include <stdint.h>

#define S_LEN 2048
#define B_SZ  64
#define XDIM  64
#define HDIM  256
#define ODIM  64
#define NTILES_C 4096                     // (S_LEN*B_SZ)/32

// Scratch (alloc-free rule: __device__ globals)
__device__ float g_U[S_LEN * B_SZ * HDIM];   // U[t,b,:] = feat @ Wih^T + bih + bhh
__device__ float g_Hs[S_LEN * B_SZ * HDIM];  // hidden state ENTERING step t (h_0 = 0)
__device__ unsigned g_cntH[128];             // per-16-step completion counters
__device__ unsigned g_tick;                  // kC tile ticket queue

// ------------------------- packed fp32x2 helpers ---------------------------
__device__ __forceinline__ unsigned long long fma2(unsigned long long a,
                                                   unsigned long long b,
                                                   unsigned long long c) {
    unsigned long long d;
    asm("fma.rn.f32x2 %0, %1, %2, %3;" : "=l"(d) : "l"(a), "l"(b), "l"(c));
    return d;
}
__device__ __forceinline__ unsigned long long add2(unsigned long long a,
                                                   unsigned long long b) {
    unsigned long long d;
    asm("add.rn.f32x2 %0, %1, %2;" : "=l"(d) : "l"(a), "l"(b));
    return d;
}
__device__ __forceinline__ float pk_lo(unsigned long long v) {
    return __uint_as_float((unsigned)(v & 0xffffffffull));
}
__device__ __forceinline__ float pk_hi(unsigned long long v) {
    return __uint_as_float((unsigned)(v >> 32));
}
__device__ __forceinline__ unsigned long long pk2(float v) {
    unsigned long long d;
    unsigned u = __float_as_uint(v);
    asm("mov.b64 %0, {%1, %2};" : "=l"(d) : "r"(u), "r"(u));
    return d;
}

__device__ __forceinline__ uint32_t smem_u32(const void* p) {
    uint32_t a;
    asm("{ .reg .u64 t; cvta.to.shared.u64 t, %1; cvt.u32.u64 %0, t; }"
        : "=r"(a) : "l"(p));
    return a;
}
__device__ __forceinline__ uint32_t ctarank() {
    uint32_t r;
    asm("mov.u32 %0, %%cluster_ctarank;" : "=r"(r));
    return r;
}
__device__ __forceinline__ void st_async_peer_f32(uint32_t daddr, uint32_t mbaddr,
                                                  uint32_t peer, float v) {
    asm volatile(
        "{\n\t.reg .b32 ra, rb;\n\t"
        "mapa.shared::cluster.u32 ra, %0, %2;\n\t"
        "mapa.shared::cluster.u32 rb, %1, %2;\n\t"
        "st.async.shared::cluster.mbarrier::complete_tx::bytes.f32 [ra], %3, [rb];\n\t}"
        :: "r"(daddr), "r"(mbaddr), "r"(peer), "f"(v) : "memory");
}
__device__ __forceinline__ void mbar_init(uint32_t addr, uint32_t cnt) {
    asm volatile("mbarrier.init.shared.b64 [%0], %1;" :: "r"(addr), "r"(cnt) : "memory");
}
__device__ __forceinline__ void mbar_expect_tx(uint32_t addr, uint32_t bytes) {
    asm volatile("mbarrier.arrive.expect_tx.shared.b64 _, [%0], %1;"
                 :: "r"(addr), "r"(bytes) : "memory");
}
__device__ __forceinline__ void mbar_wait_cta(uint32_t addr, uint32_t parity) {
    asm volatile(
        "{\n\t.reg .pred P;\n\t"
        "W_%=:\n\t"
        "mbarrier.try_wait.parity.acquire.cta.shared::cta.b64 P, [%0], %1, 0x989680;\n\t"
        "@!P bra W_%=;\n\t}"
        :: "r"(addr), "r"(parity) : "memory");
}
__device__ __forceinline__ unsigned ld_acq(const unsigned* p) {
    unsigned v;
    asm volatile("ld.acquire.gpu.global.u32 %0, [%1];" : "=r"(v) : "l"(p));
    return v;
}
__device__ __forceinline__ void flag_release(unsigned* p) {
    asm volatile("fence.acq_rel.gpu;" ::: "memory");
    asm volatile("red.release.gpu.global.add.u32 [%0], 1;" :: "l"(p) : "memory");
}

// ---------------------------------------------------------------------------
// Kernel A v2 (R10): feat = tanh(x @ Wx + bx); U = feat @ Wih^T + (bih + bhh)
// Also resets the ticket/flag state for this launch (graph-replay safe).
// ---------------------------------------------------------------------------
__global__ __launch_bounds__(256, 1) void kA(
    const float* __restrict__ x,
    const float* __restrict__ Wx, const float* __restrict__ bx,
    const float* __restrict__ Wih, const float* __restrict__ bih,
    const float* __restrict__ bhh)
{
    extern __shared__ float sm[];
    float* sWx   = sm;                    // [64][128]
    float* sWihT = sWx + 64 * 128;        // [128][260]
    float* sbx   = sWihT + 128 * 260;     // [128]
    float* sbU   = sbx + 128;             // [256]
    float* sx    = sbU + 256;             // [32][64]
    float* sfeat = sx + 32 * 64;          // [32][128]

    const int t = threadIdx.x;

    if (blockIdx.x == 0) {                // reset flags/ticket for this launch
        if (t < 128) g_cntH[t] = 0u;
        if (t == 128) g_tick = 0u;
    }

    for (int idx = t; idx < 64 * 128; idx += 256) sWx[idx] = Wx[idx];
    for (int idx = t; idx < 256 * 128; idx += 256) {
        int i = idx >> 7, j = idx & 127;
        sWihT[j * 260 + i] = Wih[idx];
    }
    if (t < 128) sbx[t] = bx[t];
    sbU[t] = bih[t] + bhh[t];
    __syncthreads();

    const int rg = t >> 6;
    const int c2 = t & 63;
    const int ii = c2 * 4;
    const int ntiles = (S_LEN * B_SZ) / 32;

    for (int tile = blockIdx.x; tile < ntiles; tile += gridDim.x) {
        const int row0 = tile * 32;
        {
            const float4* src = (const float4*)(x + (size_t)row0 * XDIM);
            ((float4*)sx)[t]       = src[t];
            ((float4*)sx)[t + 256] = src[t + 256];
        }
        __syncthreads();

        unsigned long long a[8];
        #pragma unroll
        for (int q = 0; q < 8; q++) a[q] = 0ull;
        #pragma unroll 2
        for (int k4 = 0; k4 < 64; k4 += 4) {
            float xv[8][4];
            #pragma unroll
            for (int q = 0; q < 8; q++)
                *(float4*)&xv[q][0] = *(const float4*)&sx[(rg * 8 + q) * 64 + k4];
            #pragma unroll
            for (int s = 0; s < 4; s++) {
                unsigned long long w =
                    *(const unsigned long long*)&sWx[(k4 + s) * 128 + 2 * c2];
                #pragma unroll
                for (int q = 0; q < 8; q++)
                    a[q] = fma2(pk2(xv[q][s]), w, a[q]);
            }
        }
        {
            const float bx0 = sbx[2 * c2], bx1 = sbx[2 * c2 + 1];
            #pragma unroll
            for (int q = 0; q < 8; q++) {
                const int row = rg * 8 + q;
                sfeat[row * 128 + 2 * c2]     = tanhf(pk_lo(a[q]) + bx0);
                sfeat[row * 128 + 2 * c2 + 1] = tanhf(pk_hi(a[q]) + bx1);
            }
        }
        __syncthreads();

        unsigned long long acc01[8], acc23[8];
        #pragma unroll
        for (int q = 0; q < 8; q++) { acc01[q] = 0ull; acc23[q] = 0ull; }
        #pragma unroll 2
        for (int j4 = 0; j4 < 128; j4 += 4) {
            float f[8][4];
            #pragma unroll
            for (int q = 0; q < 8; q++)
                *(float4*)&f[q][0] = *(const float4*)&sfeat[(rg * 8 + q) * 128 + j4];
            #pragma unroll
            for (int s = 0; s < 4; s++) {
                ulonglong2 w = *(const ulonglong2*)&sWihT[(j4 + s) * 260 + ii];
                #pragma unroll
                for (int q = 0; q < 8; q++) {
                    unsigned long long fs = pk2(f[q][s]);
                    acc01[q] = fma2(fs, w.x, acc01[q]);
                    acc23[q] = fma2(fs, w.y, acc23[q]);
                }
            }
        }
        float4 bU = *(const float4*)&sbU[ii];
        #pragma unroll
        for (int q = 0; q < 8; q++) {
            float4 o;
            o.x = pk_lo(acc01[q]) + bU.x; o.y = pk_hi(acc01[q]) + bU.y;
            o.z = pk_lo(acc23[q]) + bU.z; o.w = pk_hi(acc23[q]) + bU.w;
            *((float4*)&g_U[(size_t)(row0 + rg * 8 + q) * HDIM + ii]) = o;
        }
        __syncthreads();
    }
}

// ---------------------------------------------------------------------------
// kC tile worker (R10 kC v2 body + ticket queue + readiness flags).
// Processes 32-row tiles of: z = tanh(h @ Whx + bhx); y = z @ Wout + bout.
// tile k covers rows [32k, 32k+32) = time t = k>>1; ready when flag slot
// (k>>5) has all 128 recurrence-CTA increments.
// ---------------------------------------------------------------------------
__device__ void kc_worker(
    float* sm,
    const float* __restrict__ Whx, const float* __restrict__ bhx,
    const float* __restrict__ Wout, const float* __restrict__ bout,
    float* __restrict__ y)
{
    float* sWhx  = sm;                   // [256][128]
    float* sWout = sWhx + 256 * 128;     // [128][64]
    float* sbhx  = sWout + 128 * 64;     // [128]
    float* sbout = sbhx + 128;           // [64]
    float* sht   = sbout + 64;           // [32][256]
    float* sz    = sht + 32 * 256;       // [32][128]

    __shared__ int s_tile;

    const int t = threadIdx.x;
    for (int idx = t; idx < 256 * 128; idx += 256) sWhx[idx] = Whx[idx];
    for (int idx = t; idx < 128 * 64; idx += 256) sWout[idx] = Wout[idx];
    if (t < 128) sbhx[t] = bhx[t];
    if (t < 64)  sbout[t] = bout[t];
    __syncthreads();

    const int rg  = t >> 5;
    const int jj4 = (t & 31) * 4;
    const int rr  = t >> 4;
    const int oo4 = (t & 15) * 4;

    for (;;) {
        if (t == 0) s_tile = (int)atomicAdd(&g_tick, 1u);
        __syncthreads();
        const int tile = s_tile;
        if (tile >= NTILES_C) break;

        if (t == 0) {                     // wait until g_Hs for this tile is live
            while (ld_acq(&g_cntH[tile >> 5]) < 128u) __nanosleep(256);
        }
        __syncthreads();

        const int row0 = tile * 32;
        {
            const float4* src = (const float4*)(g_Hs + (size_t)row0 * HDIM);
            float4* dst = (float4*)sht;
            #pragma unroll
            for (int q = 0; q < 8; q++) dst[q * 256 + t] = src[q * 256 + t];
        }
        __syncthreads();

        // phase 1: z = tanh(h @ Whx + bhx)
        unsigned long long acc01[4], acc23[4];
        #pragma unroll
        for (int q = 0; q < 4; q++) { acc01[q] = 0ull; acc23[q] = 0ull; }
        #pragma unroll 2
        for (int i4 = 0; i4 < 256; i4 += 4) {
            float hq[4][4];
            #pragma unroll
            for (int q = 0; q < 4; q++)
                *(float4*)&hq[q][0] = *(const float4*)&sht[(rg * 4 + q) * 256 + i4];
            #pragma unroll
            for (int s = 0; s < 4; s++) {
                ulonglong2 w = *(const ulonglong2*)&sWhx[(i4 + s) * 128 + jj4];
                #pragma unroll
                for (int q = 0; q < 4; q++) {
                    unsigned long long hs = pk2(hq[q][s]);
                    acc01[q] = fma2(hs, w.x, acc01[q]);
                    acc23[q] = fma2(hs, w.y, acc23[q]);
                }
            }
        }
        float4 bz = *(const float4*)&sbhx[jj4];
        #pragma unroll
        for (int q = 0; q < 4; q++) {
            const int rw = rg * 4 + q;
            sz[rw * 128 + jj4 + 0] = tanhf(pk_lo(acc01[q]) + bz.x);
            sz[rw * 128 + jj4 + 1] = tanhf(pk_hi(acc01[q]) + bz.y);
            sz[rw * 128 + jj4 + 2] = tanhf(pk_lo(acc23[q]) + bz.z);
            sz[rw * 128 + jj4 + 3] = tanhf(pk_hi(acc23[q]) + bz.w);
        }
        __syncthreads();

        // phase 2: y = z @ Wout + bout
        float4 o[2];
        o[0] = make_float4(0.f, 0.f, 0.f, 0.f);
        o[1] = make_float4(0.f, 0.f, 0.f, 0.f);
        #pragma unroll 2
        for (int j4 = 0; j4 < 128; j4 += 4) {
            float zq[2][4];
            #pragma unroll
            for (int q2 = 0; q2 < 2; q2++)
                *(float4*)&zq[q2][0] = *(const float4*)&sz[(rr * 2 + q2) * 128 + j4];
            #pragma unroll
            for (int s = 0; s < 4; s++) {
                float4 w = *(const float4*)&sWout[(j4 + s) * 64 + oo4];
                #pragma unroll
                for (int q2 = 0; q2 < 2; q2++) {
                    o[q2].x = fmaf(zq[q2][s], w.x, o[q2].x);
                    o[q2].y = fmaf(zq[q2][s], w.y, o[q2].y);
                    o[q2].z = fmaf(zq[q2][s], w.z, o[q2].z);
                    o[q2].w = fmaf(zq[q2][s], w.w, o[q2].w);
                }
            }
        }
        float4 bo = *(const float4*)&sbout[oo4];
        #pragma unroll
        for (int q2 = 0; q2 < 2; q2++) {
            float4 ov;
            ov.x = o[q2].x + bo.x; ov.y = o[q2].y + bo.y;
            ov.z = o[q2].z + bo.z; ov.w = o[q2].w + bo.w;
            *((float4*)&y[(size_t)(row0 + rr * 2 + q2) * ODIM + oo4]) = ov;
        }
        __syncthreads();
    }
}

// ---------------------------------------------------------------------------
// Mega-kernel: CTAs 0..127 = kB v4 recurrence (byte-identical math) with
// per-16-step release flags; CTAs 128..147 = kC workers from launch; the
// recurrence CTAs join the worker queue when their loop ends.
// ---------------------------------------------------------------------------
__global__ __launch_bounds__(256, 1) __cluster_dims__(2, 1, 1)
void kBC(const float* __restrict__ Whh, const float* __restrict__ sigmas,
         const float* __restrict__ Whx, const float* __restrict__ bhx,
         const float* __restrict__ Wout, const float* __restrict__ bout,
         float* __restrict__ y)
{
    extern __shared__ float dsm[];              // kC worker storage (dynamic)

    if (blockIdx.x < 128) {
        __shared__ __align__(16) float sh[2][256];
        __shared__ __align__(16) float spart[128];
        __shared__ __align__(8)  unsigned long long mbar[2];

        const int tid   = threadIdx.x;
        const int i_loc = tid & 127;
        const int half  = tid >> 7;
        const uint32_t rank = ctarank();
        const uint32_t peer = rank ^ 1u;
        const int r  = (int)rank;
        const int b  = blockIdx.x >> 1;
        const int gi = r * 128 + i_loc;
        const bool fresh     = (half == r);
        const bool finalizer = (half == 0);
        const int waiter_leader = (r == 0) ? 128 : 0;

        ulonglong2 wreg[32];
        {
            const ulonglong2* ws =
                (const ulonglong2*)(Whh + (size_t)gi * HDIM + 128 * half);
            #pragma unroll
            for (int i = 0; i < 32; i++) wreg[i] = ws[i];
        }

        const float alpha = 1.0f / (1.0f + expf(-sigmas[gi & 3]));
        const float oma   = 1.0f - alpha;

        sh[0][tid] = 0.f;
        sh[1][tid] = 0.f;
        const uint32_t mb[2] = { smem_u32(&mbar[0]), smem_u32(&mbar[1]) };
        const uint32_t sh_a  = smem_u32(&sh[0][0]);
        if (tid == 0) { mbar_init(mb[0], 1); mbar_init(mb[1], 1); }
        __syncthreads();
        if (tid == waiter_leader) {
            mbar_expect_tx(mb[0], 512);
            mbar_expect_tx(mb[1], 512);
        }
        __syncthreads();
        asm volatile("barrier.cluster.arrive.aligned;" ::: "memory");
        asm volatile("barrier.cluster.wait.aligned;" ::: "memory");

        float h_reg  = 0.f;
        float u_next = finalizer ? g_U[(size_t)b * HDIM + gi] : 0.f;

        for (int t = 0; t < S_LEN; t++) {
            const float* hsrc = sh[(t + 1) & 1] + 128 * half;

            if (!fresh && t > 0) {
                const int pm = (t - 1) & 1;
                mbar_wait_cta(mb[pm], (uint32_t)(((t - 1) >> 1) & 1));
                if (tid == waiter_leader)
                    mbar_expect_tx(mb[pm], 512);
            }

            unsigned long long a0 = 0ull, a1 = 0ull, a2 = 0ull, a3 = 0ull;
            #pragma unroll
            for (int i = 0; i < 32; i += 2) {
                ulonglong2 h0 = *(const ulonglong2*)&hsrc[i * 4];
                a0 = fma2(wreg[i].x, h0.x, a0);
                a1 = fma2(wreg[i].y, h0.y, a1);
                ulonglong2 h1 = *(const ulonglong2*)&hsrc[i * 4 + 4];
                a2 = fma2(wreg[i + 1].x, h1.x, a2);
                a3 = fma2(wreg[i + 1].y, h1.y, a3);
            }
            unsigned long long c = add2(add2(a0, a1), add2(a2, a3));
            const float partial = pk_lo(c) + pk_hi(c);

            if (!finalizer) spart[i_loc] = partial;
            __syncthreads();

            if (finalizer) {
                const float u = u_next;
                if (t + 1 < S_LEN)
                    u_next = g_U[((size_t)(t + 1) * B_SZ + b) * HDIM + gi];
                g_Hs[((size_t)t * B_SZ + b) * HDIM + gi] = h_reg;

                const float s  = partial + spart[i_loc] + u;
                const float hn = tanhf(s);
                h_reg = oma * h_reg + alpha * hn;

                const int wb = t & 1;
                sh[wb][gi] = h_reg;
                st_async_peer_f32(sh_a + (uint32_t)((wb * 256 + gi) * 4),
                                  mb[wb], peer, h_reg);
            }
            __syncthreads();

            // publish g_Hs progress every 16 steps (off critical path: 1 thread)
            if (((t & 15) == 15) && tid == 0)
                flag_release(&g_cntH[t >> 4]);
        }

        asm volatile("barrier.cluster.arrive.aligned;" ::: "memory");
        asm volatile("barrier.cluster.wait.aligned;" ::: "memory");
    }

    // Everyone (workers from launch; recurrence CTAs afterwards) drains tiles.
    kc_worker(dsm, Whx, bhx, Wout, bout, y);
}

// ---------------------------------------------------------------------------
extern "C" void kernel_launch(void* const* d_in, const int* in_sizes, int n_in,
                              void* d_out, int out_size)
{
    const float* x      = (const float*)d_in[0];
    const float* Wx     = (const float*)d_in[1];
    const float* bx     = (const float*)d_in[2];
    const float* Wih    = (const float*)d_in[3];
    const float* bih    = (const float*)d_in[4];
    const float* Whh    = (const float*)d_in[5];
    const float* bhh    = (const float*)d_in[6];
    const float* Whx    = (const float*)d_in[7];
    const float* bhx    = (const float*)d_in[8];
    const float* Wout   = (const float*)d_in[9];
    const float* bout   = (const float*)d_in[10];
    const float* sigmas = (const float*)d_in[11];
    float* y = (float*)d_out;

    const size_t smA = (size_t)(64*128 + 128*260 + 128 + 256 + 32*64 + 32*128) * 4;
    const size_t smC = (size_t)(256*128 + 128*64 + 128 + 64 + 32*256 + 32*128) * 4;

    cudaFuncSetAttribute(kA, cudaFuncAttributeMaxDynamicSharedMemorySize, (int)smA);
    cudaFuncSetAttribute(kBC, cudaFuncAttributeMaxDynamicSharedMemorySize, (int)smC);

    kA<<<148, 256, smA>>>(x, Wx, bx, Wih, bih, bhh);
    kBC<<<148, 256, smC>>>(Whh, sigmas, Whx, bhx, Wout, bout, y);
}

// round 15
// speedup vs baseline: 2.6092x; 1.0060x over previous
#include <cuda_runtime.h>
#include <math.h>
#include <stdint.h>

#define S_LEN 2048
#define B_SZ  64
#define XDIM  64
#define HDIM  256
#define ODIM  64
#define NTILES_C 4096                     // (S_LEN*B_SZ)/32

// Scratch (alloc-free rule: __device__ globals)
__device__ float g_U[S_LEN * B_SZ * HDIM];   // U[t,b,:] = feat @ Wih^T + bih + bhh
__device__ float g_Hs[S_LEN * B_SZ * HDIM];  // hidden state ENTERING step t (h_0 = 0)
__device__ unsigned g_cntH[128];             // per-16-step completion counters
__device__ unsigned g_tick;                  // kC tile ticket queue

// ------------------------- packed fp32x2 helpers ---------------------------
__device__ __forceinline__ unsigned long long fma2(unsigned long long a,
                                                   unsigned long long b,
                                                   unsigned long long c) {
    unsigned long long d;
    asm("fma.rn.f32x2 %0, %1, %2, %3;" : "=l"(d) : "l"(a), "l"(b), "l"(c));
    return d;
}
__device__ __forceinline__ unsigned long long add2(unsigned long long a,
                                                   unsigned long long b) {
    unsigned long long d;
    asm("add.rn.f32x2 %0, %1, %2;" : "=l"(d) : "l"(a), "l"(b));
    return d;
}
__device__ __forceinline__ float pk_lo(unsigned long long v) {
    return __uint_as_float((unsigned)(v & 0xffffffffull));
}
__device__ __forceinline__ float pk_hi(unsigned long long v) {
    return __uint_as_float((unsigned)(v >> 32));
}
__device__ __forceinline__ unsigned long long pk2(float v) {
    unsigned long long d;
    unsigned u = __float_as_uint(v);
    asm("mov.b64 %0, {%1, %2};" : "=l"(d) : "r"(u), "r"(u));
    return d;
}

__device__ __forceinline__ uint32_t smem_u32(const void* p) {
    uint32_t a;
    asm("{ .reg .u64 t; cvta.to.shared.u64 t, %1; cvt.u32.u64 %0, t; }"
        : "=r"(a) : "l"(p));
    return a;
}
__device__ __forceinline__ uint32_t ctarank() {
    uint32_t r;
    asm("mov.u32 %0, %%cluster_ctarank;" : "=r"(r));
    return r;
}
__device__ __forceinline__ void st_async_peer_f32(uint32_t daddr, uint32_t mbaddr,
                                                  uint32_t peer, float v) {
    asm volatile(
        "{\n\t.reg .b32 ra, rb;\n\t"
        "mapa.shared::cluster.u32 ra, %0, %2;\n\t"
        "mapa.shared::cluster.u32 rb, %1, %2;\n\t"
        "st.async.shared::cluster.mbarrier::complete_tx::bytes.f32 [ra], %3, [rb];\n\t}"
        :: "r"(daddr), "r"(mbaddr), "r"(peer), "f"(v) : "memory");
}
__device__ __forceinline__ void mbar_init(uint32_t addr, uint32_t cnt) {
    asm volatile("mbarrier.init.shared.b64 [%0], %1;" :: "r"(addr), "r"(cnt) : "memory");
}
__device__ __forceinline__ void mbar_expect_tx(uint32_t addr, uint32_t bytes) {
    asm volatile("mbarrier.arrive.expect_tx.shared.b64 _, [%0], %1;"
                 :: "r"(addr), "r"(bytes) : "memory");
}
__device__ __forceinline__ void mbar_wait_cta(uint32_t addr, uint32_t parity) {
    asm volatile(
        "{\n\t.reg .pred P;\n\t"
        "W_%=:\n\t"
        "mbarrier.try_wait.parity.acquire.cta.shared::cta.b64 P, [%0], %1, 0x989680;\n\t"
        "@!P bra W_%=;\n\t}"
        :: "r"(addr), "r"(parity) : "memory");
}
__device__ __forceinline__ unsigned ld_acq(const unsigned* p) {
    unsigned v;
    asm volatile("ld.acquire.gpu.global.u32 %0, [%1];" : "=r"(v) : "l"(p));
    return v;
}
__device__ __forceinline__ void flag_release(unsigned* p) {
    asm volatile("fence.acq_rel.gpu;" ::: "memory");
    asm volatile("red.release.gpu.global.add.u32 [%0], 1;" :: "l"(p) : "memory");
}

// ---------------------------------------------------------------------------
// Kernel A v3: same math as v2 (bit-identical g_U), but 2 CTAs/SM (grid 296,
// __launch_bounds__(256,2)) — R10 profile showed occ=12.5%, issue=38%,
// fma=51%: latency-limited by thin occupancy. 105 regs x 512 thr and
// 2 x 48.25KB smem both fit. Also resets ticket/flag state for this launch.
// ---------------------------------------------------------------------------
__global__ __launch_bounds__(256, 2) void kA(
    const float* __restrict__ x,
    const float* __restrict__ Wx, const float* __restrict__ bx,
    const float* __restrict__ Wih, const float* __restrict__ bih,
    const float* __restrict__ bhh)
{
    extern __shared__ float sm[];
    float* sWx   = sm;                    // [64][128]
    float* sWihT = sWx + 64 * 128;        // [128][260]
    float* sbx   = sWihT + 128 * 260;     // [128]
    float* sbU   = sbx + 128;             // [256]
    float* sx    = sbU + 256;             // [32][64]
    float* sfeat = sx + 32 * 64;          // [32][128]

    const int t = threadIdx.x;

    if (blockIdx.x == 0) {                // reset flags/ticket for this launch
        if (t < 128) g_cntH[t] = 0u;
        if (t == 128) g_tick = 0u;
    }

    for (int idx = t; idx < 64 * 128; idx += 256) sWx[idx] = Wx[idx];
    for (int idx = t; idx < 256 * 128; idx += 256) {
        int i = idx >> 7, j = idx & 127;
        sWihT[j * 260 + i] = Wih[idx];
    }
    if (t < 128) sbx[t] = bx[t];
    sbU[t] = bih[t] + bhh[t];
    __syncthreads();

    const int rg = t >> 6;
    const int c2 = t & 63;
    const int ii = c2 * 4;
    const int ntiles = (S_LEN * B_SZ) / 32;

    for (int tile = blockIdx.x; tile < ntiles; tile += gridDim.x) {
        const int row0 = tile * 32;
        {
            const float4* src = (const float4*)(x + (size_t)row0 * XDIM);
            ((float4*)sx)[t]       = src[t];
            ((float4*)sx)[t + 256] = src[t + 256];
        }
        __syncthreads();

        unsigned long long a[8];
        #pragma unroll
        for (int q = 0; q < 8; q++) a[q] = 0ull;
        #pragma unroll 2
        for (int k4 = 0; k4 < 64; k4 += 4) {
            float xv[8][4];
            #pragma unroll
            for (int q = 0; q < 8; q++)
                *(float4*)&xv[q][0] = *(const float4*)&sx[(rg * 8 + q) * 64 + k4];
            #pragma unroll
            for (int s = 0; s < 4; s++) {
                unsigned long long w =
                    *(const unsigned long long*)&sWx[(k4 + s) * 128 + 2 * c2];
                #pragma unroll
                for (int q = 0; q < 8; q++)
                    a[q] = fma2(pk2(xv[q][s]), w, a[q]);
            }
        }
        {
            const float bx0 = sbx[2 * c2], bx1 = sbx[2 * c2 + 1];
            #pragma unroll
            for (int q = 0; q < 8; q++) {
                const int row = rg * 8 + q;
                sfeat[row * 128 + 2 * c2]     = tanhf(pk_lo(a[q]) + bx0);
                sfeat[row * 128 + 2 * c2 + 1] = tanhf(pk_hi(a[q]) + bx1);
            }
        }
        __syncthreads();

        unsigned long long acc01[8], acc23[8];
        #pragma unroll
        for (int q = 0; q < 8; q++) { acc01[q] = 0ull; acc23[q] = 0ull; }
        #pragma unroll 2
        for (int j4 = 0; j4 < 128; j4 += 4) {
            float f[8][4];
            #pragma unroll
            for (int q = 0; q < 8; q++)
                *(float4*)&f[q][0] = *(const float4*)&sfeat[(rg * 8 + q) * 128 + j4];
            #pragma unroll
            for (int s = 0; s < 4; s++) {
                ulonglong2 w = *(const ulonglong2*)&sWihT[(j4 + s) * 260 + ii];
                #pragma unroll
                for (int q = 0; q < 8; q++) {
                    unsigned long long fs = pk2(f[q][s]);
                    acc01[q] = fma2(fs, w.x, acc01[q]);
                    acc23[q] = fma2(fs, w.y, acc23[q]);
                }
            }
        }
        float4 bU = *(const float4*)&sbU[ii];
        #pragma unroll
        for (int q = 0; q < 8; q++) {
            float4 o;
            o.x = pk_lo(acc01[q]) + bU.x; o.y = pk_hi(acc01[q]) + bU.y;
            o.z = pk_lo(acc23[q]) + bU.z; o.w = pk_hi(acc23[q]) + bU.w;
            *((float4*)&g_U[(size_t)(row0 + rg * 8 + q) * HDIM + ii]) = o;
        }
        __syncthreads();
    }
}

// ---------------------------------------------------------------------------
// kC tile worker (R14, unchanged): ticket queue + readiness flags.
// ---------------------------------------------------------------------------
__device__ void kc_worker(
    float* sm,
    const float* __restrict__ Whx, const float* __restrict__ bhx,
    const float* __restrict__ Wout, const float* __restrict__ bout,
    float* __restrict__ y)
{
    float* sWhx  = sm;                   // [256][128]
    float* sWout = sWhx + 256 * 128;     // [128][64]
    float* sbhx  = sWout + 128 * 64;     // [128]
    float* sbout = sbhx + 128;           // [64]
    float* sht   = sbout + 64;           // [32][256]
    float* sz    = sht + 32 * 256;       // [32][128]

    __shared__ int s_tile;

    const int t = threadIdx.x;
    for (int idx = t; idx < 256 * 128; idx += 256) sWhx[idx] = Whx[idx];
    for (int idx = t; idx < 128 * 64; idx += 256) sWout[idx] = Wout[idx];
    if (t < 128) sbhx[t] = bhx[t];
    if (t < 64)  sbout[t] = bout[t];
    __syncthreads();

    const int rg  = t >> 5;
    const int jj4 = (t & 31) * 4;
    const int rr  = t >> 4;
    const int oo4 = (t & 15) * 4;

    for (;;) {
        if (t == 0) s_tile = (int)atomicAdd(&g_tick, 1u);
        __syncthreads();
        const int tile = s_tile;
        if (tile >= NTILES_C) break;

        if (t == 0) {                     // wait until g_Hs for this tile is live
            while (ld_acq(&g_cntH[tile >> 5]) < 128u) __nanosleep(256);
        }
        __syncthreads();

        const int row0 = tile * 32;
        {
            const float4* src = (const float4*)(g_Hs + (size_t)row0 * HDIM);
            float4* dst = (float4*)sht;
            #pragma unroll
            for (int q = 0; q < 8; q++) dst[q * 256 + t] = src[q * 256 + t];
        }
        __syncthreads();

        // phase 1: z = tanh(h @ Whx + bhx)
        unsigned long long acc01[4], acc23[4];
        #pragma unroll
        for (int q = 0; q < 4; q++) { acc01[q] = 0ull; acc23[q] = 0ull; }
        #pragma unroll 2
        for (int i4 = 0; i4 < 256; i4 += 4) {
            float hq[4][4];
            #pragma unroll
            for (int q = 0; q < 4; q++)
                *(float4*)&hq[q][0] = *(const float4*)&sht[(rg * 4 + q) * 256 + i4];
            #pragma unroll
            for (int s = 0; s < 4; s++) {
                ulonglong2 w = *(const ulonglong2*)&sWhx[(i4 + s) * 128 + jj4];
                #pragma unroll
                for (int q = 0; q < 4; q++) {
                    unsigned long long hs = pk2(hq[q][s]);
                    acc01[q] = fma2(hs, w.x, acc01[q]);
                    acc23[q] = fma2(hs, w.y, acc23[q]);
                }
            }
        }
        float4 bz = *(const float4*)&sbhx[jj4];
        #pragma unroll
        for (int q = 0; q < 4; q++) {
            const int rw = rg * 4 + q;
            sz[rw * 128 + jj4 + 0] = tanhf(pk_lo(acc01[q]) + bz.x);
            sz[rw * 128 + jj4 + 1] = tanhf(pk_hi(acc01[q]) + bz.y);
            sz[rw * 128 + jj4 + 2] = tanhf(pk_lo(acc23[q]) + bz.z);
            sz[rw * 128 + jj4 + 3] = tanhf(pk_hi(acc23[q]) + bz.w);
        }
        __syncthreads();

        // phase 2: y = z @ Wout + bout
        float4 o[2];
        o[0] = make_float4(0.f, 0.f, 0.f, 0.f);
        o[1] = make_float4(0.f, 0.f, 0.f, 0.f);
        #pragma unroll 2
        for (int j4 = 0; j4 < 128; j4 += 4) {
            float zq[2][4];
            #pragma unroll
            for (int q2 = 0; q2 < 2; q2++)
                *(float4*)&zq[q2][0] = *(const float4*)&sz[(rr * 2 + q2) * 128 + j4];
            #pragma unroll
            for (int s = 0; s < 4; s++) {
                float4 w = *(const float4*)&sWout[(j4 + s) * 64 + oo4];
                #pragma unroll
                for (int q2 = 0; q2 < 2; q2++) {
                    o[q2].x = fmaf(zq[q2][s], w.x, o[q2].x);
                    o[q2].y = fmaf(zq[q2][s], w.y, o[q2].y);
                    o[q2].z = fmaf(zq[q2][s], w.z, o[q2].z);
                    o[q2].w = fmaf(zq[q2][s], w.w, o[q2].w);
                }
            }
        }
        float4 bo = *(const float4*)&sbout[oo4];
        #pragma unroll
        for (int q2 = 0; q2 < 2; q2++) {
            float4 ov;
            ov.x = o[q2].x + bo.x; ov.y = o[q2].y + bo.y;
            ov.z = o[q2].z + bo.z; ov.w = o[q2].w + bo.w;
            *((float4*)&y[(size_t)(row0 + rr * 2 + q2) * ODIM + oo4]) = ov;
        }
        __syncthreads();
    }
}

// ---------------------------------------------------------------------------
// Mega-kernel (R14, unchanged): CTAs 0..127 = kB v4 recurrence with per-16-
// step release flags; CTAs 128..147 = kC workers; recurrence CTAs join the
// worker queue when their loop ends.
// ---------------------------------------------------------------------------
__global__ __launch_bounds__(256, 1) __cluster_dims__(2, 1, 1)
void kBC(const float* __restrict__ Whh, const float* __restrict__ sigmas,
         const float* __restrict__ Whx, const float* __restrict__ bhx,
         const float* __restrict__ Wout, const float* __restrict__ bout,
         float* __restrict__ y)
{
    extern __shared__ float dsm[];              // kC worker storage (dynamic)

    if (blockIdx.x < 128) {
        __shared__ __align__(16) float sh[2][256];
        __shared__ __align__(16) float spart[128];
        __shared__ __align__(8)  unsigned long long mbar[2];

        const int tid   = threadIdx.x;
        const int i_loc = tid & 127;
        const int half  = tid >> 7;
        const uint32_t rank = ctarank();
        const uint32_t peer = rank ^ 1u;
        const int r  = (int)rank;
        const int b  = blockIdx.x >> 1;
        const int gi = r * 128 + i_loc;
        const bool fresh     = (half == r);
        const bool finalizer = (half == 0);
        const int waiter_leader = (r == 0) ? 128 : 0;

        ulonglong2 wreg[32];
        {
            const ulonglong2* ws =
                (const ulonglong2*)(Whh + (size_t)gi * HDIM + 128 * half);
            #pragma unroll
            for (int i = 0; i < 32; i++) wreg[i] = ws[i];
        }

        const float alpha = 1.0f / (1.0f + expf(-sigmas[gi & 3]));
        const float oma   = 1.0f - alpha;

        sh[0][tid] = 0.f;
        sh[1][tid] = 0.f;
        const uint32_t mb[2] = { smem_u32(&mbar[0]), smem_u32(&mbar[1]) };
        const uint32_t sh_a  = smem_u32(&sh[0][0]);
        if (tid == 0) { mbar_init(mb[0], 1); mbar_init(mb[1], 1); }
        __syncthreads();
        if (tid == waiter_leader) {
            mbar_expect_tx(mb[0], 512);
            mbar_expect_tx(mb[1], 512);
        }
        __syncthreads();
        asm volatile("barrier.cluster.arrive.aligned;" ::: "memory");
        asm volatile("barrier.cluster.wait.aligned;" ::: "memory");

        float h_reg  = 0.f;
        float u_next = finalizer ? g_U[(size_t)b * HDIM + gi] : 0.f;

        for (int t = 0; t < S_LEN; t++) {
            const float* hsrc = sh[(t + 1) & 1] + 128 * half;

            if (!fresh && t > 0) {
                const int pm = (t - 1) & 1;
                mbar_wait_cta(mb[pm], (uint32_t)(((t - 1) >> 1) & 1));
                if (tid == waiter_leader)
                    mbar_expect_tx(mb[pm], 512);
            }

            unsigned long long a0 = 0ull, a1 = 0ull, a2 = 0ull, a3 = 0ull;
            #pragma unroll
            for (int i = 0; i < 32; i += 2) {
                ulonglong2 h0 = *(const ulonglong2*)&hsrc[i * 4];
                a0 = fma2(wreg[i].x, h0.x, a0);
                a1 = fma2(wreg[i].y, h0.y, a1);
                ulonglong2 h1 = *(const ulonglong2*)&hsrc[i * 4 + 4];
                a2 = fma2(wreg[i + 1].x, h1.x, a2);
                a3 = fma2(wreg[i + 1].y, h1.y, a3);
            }
            unsigned long long c = add2(add2(a0, a1), add2(a2, a3));
            const float partial = pk_lo(c) + pk_hi(c);

            if (!finalizer) spart[i_loc] = partial;
            __syncthreads();

            if (finalizer) {
                const float u = u_next;
                if (t + 1 < S_LEN)
                    u_next = g_U[((size_t)(t + 1) * B_SZ + b) * HDIM + gi];
                g_Hs[((size_t)t * B_SZ + b) * HDIM + gi] = h_reg;

                const float s  = partial + spart[i_loc] + u;
                const float hn = tanhf(s);
                h_reg = oma * h_reg + alpha * hn;

                const int wb = t & 1;
                sh[wb][gi] = h_reg;
                st_async_peer_f32(sh_a + (uint32_t)((wb * 256 + gi) * 4),
                                  mb[wb], peer, h_reg);
            }
            __syncthreads();

            // publish g_Hs progress every 16 steps (1 thread, off critical path)
            if (((t & 15) == 15) && tid == 0)
                flag_release(&g_cntH[t >> 4]);
        }

        asm volatile("barrier.cluster.arrive.aligned;" ::: "memory");
        asm volatile("barrier.cluster.wait.aligned;" ::: "memory");
    }

    // Everyone (workers from launch; recurrence CTAs afterwards) drains tiles.
    kc_worker(dsm, Whx, bhx, Wout, bout, y);
}

// ---------------------------------------------------------------------------
extern "C" void kernel_launch(void* const* d_in, const int* in_sizes, int n_in,
                              void* d_out, int out_size)
{
    const float* x      = (const float*)d_in[0];
    const float* Wx     = (const float*)d_in[1];
    const float* bx     = (const float*)d_in[2];
    const float* Wih    = (const float*)d_in[3];
    const float* bih    = (const float*)d_in[4];
    const float* Whh    = (const float*)d_in[5];
    const float* bhh    = (const float*)d_in[6];
    const float* Whx    = (const float*)d_in[7];
    const float* bhx    = (const float*)d_in[8];
    const float* Wout   = (const float*)d_in[9];
    const float* bout   = (const float*)d_in[10];
    const float* sigmas = (const float*)d_in[11];
    float* y = (float*)d_out;

    const size_t smA = (size_t)(64*128 + 128*260 + 128 + 256 + 32*64 + 32*128) * 4;
    const size_t smC = (size_t)(256*128 + 128*64 + 128 + 64 + 32*256 + 32*128) * 4;

    cudaFuncSetAttribute(kA, cudaFuncAttributeMaxDynamicSharedMemorySize, (int)smA);
    cudaFuncSetAttribute(kBC, cudaFuncAttributeMaxDynamicSharedMemorySize, (int)smC);

    kA<<<296, 256, smA>>>(x, Wx, bx, Wih, bih, bhh);
    kBC<<<148, 256, smC>>>(Whh, sigmas, Whx, bhx, Wout, bout, y);
}

// round 16
// speedup vs baseline: 2.6270x; 1.0068x over previous
#include <cuda_runtime.h>
#include <math.h>
#include <stdint.h>

#define S_LEN 2048
#define B_SZ  64
#define XDIM  64
#define HDIM  256
#define ODIM  64
#define NTILES_C 4096                     // (S_LEN*B_SZ)/32

// Scratch (alloc-free rule: __device__ globals)
__device__ float g_U[S_LEN * B_SZ * HDIM];   // U[t,b,:] = feat @ Wih^T + bih + bhh
__device__ float g_Hs[S_LEN * B_SZ * HDIM];  // hidden state ENTERING step t (h_0 = 0)
__device__ unsigned g_cntH[128];             // per-16-step completion counters
__device__ unsigned g_tick;                  // kC tile ticket queue

// ------------------------- packed fp32x2 helpers ---------------------------
__device__ __forceinline__ unsigned long long fma2(unsigned long long a,
                                                   unsigned long long b,
                                                   unsigned long long c) {
    unsigned long long d;
    asm("fma.rn.f32x2 %0, %1, %2, %3;" : "=l"(d) : "l"(a), "l"(b), "l"(c));
    return d;
}
__device__ __forceinline__ unsigned long long add2(unsigned long long a,
                                                   unsigned long long b) {
    unsigned long long d;
    asm("add.rn.f32x2 %0, %1, %2;" : "=l"(d) : "l"(a), "l"(b));
    return d;
}
__device__ __forceinline__ float pk_lo(unsigned long long v) {
    return __uint_as_float((unsigned)(v & 0xffffffffull));
}
__device__ __forceinline__ float pk_hi(unsigned long long v) {
    return __uint_as_float((unsigned)(v >> 32));
}
__device__ __forceinline__ unsigned long long pk2(float v) {
    unsigned long long d;
    unsigned u = __float_as_uint(v);
    asm("mov.b64 %0, {%1, %2};" : "=l"(d) : "r"(u), "r"(u));
    return d;
}

__device__ __forceinline__ uint32_t smem_u32(const void* p) {
    uint32_t a;
    asm("{ .reg .u64 t; cvta.to.shared.u64 t, %1; cvt.u32.u64 %0, t; }"
        : "=r"(a) : "l"(p));
    return a;
}
__device__ __forceinline__ uint32_t ctarank() {
    uint32_t r;
    asm("mov.u32 %0, %%cluster_ctarank;" : "=r"(r));
    return r;
}
__device__ __forceinline__ void st_async_peer_f32(uint32_t daddr, uint32_t mbaddr,
                                                  uint32_t peer, float v) {
    asm volatile(
        "{\n\t.reg .b32 ra, rb;\n\t"
        "mapa.shared::cluster.u32 ra, %0, %2;\n\t"
        "mapa.shared::cluster.u32 rb, %1, %2;\n\t"
        "st.async.shared::cluster.mbarrier::complete_tx::bytes.f32 [ra], %3, [rb];\n\t}"
        :: "r"(daddr), "r"(mbaddr), "r"(peer), "f"(v) : "memory");
}
__device__ __forceinline__ void mbar_init(uint32_t addr, uint32_t cnt) {
    asm volatile("mbarrier.init.shared.b64 [%0], %1;" :: "r"(addr), "r"(cnt) : "memory");
}
__device__ __forceinline__ void mbar_expect_tx(uint32_t addr, uint32_t bytes) {
    asm volatile("mbarrier.arrive.expect_tx.shared.b64 _, [%0], %1;"
                 :: "r"(addr), "r"(bytes) : "memory");
}
__device__ __forceinline__ void mbar_wait_cta(uint32_t addr, uint32_t parity) {
    asm volatile(
        "{\n\t.reg .pred P;\n\t"
        "W_%=:\n\t"
        "mbarrier.try_wait.parity.acquire.cta.shared::cta.b64 P, [%0], %1, 0x989680;\n\t"
        "@!P bra W_%=;\n\t}"
        :: "r"(addr), "r"(parity) : "memory");
}
__device__ __forceinline__ unsigned ld_acq(const unsigned* p) {
    unsigned v;
    asm volatile("ld.acquire.gpu.global.u32 %0, [%1];" : "=r"(v) : "l"(p));
    return v;
}
__device__ __forceinline__ void flag_release(unsigned* p) {
    asm volatile("fence.acq_rel.gpu;" ::: "memory");
    asm volatile("red.release.gpu.global.add.u32 [%0], 1;" :: "l"(p) : "memory");
}

// ---------------------------------------------------------------------------
// Kernel A v4: same per-row math as v2/v3 (bit-identical g_U), but ONE CTA of
// 512 THREADS per SM (16 warps share the single 165KB weight image — the real
// occupancy fix; 2 CTAs/SM was impossible at 192KB smem/CTA). 64-row tiles:
// smem = 165.4K(wts) + 16K(sx) + 32K(sfeat) + eps ~= 214KB < 227KB.
// Also resets ticket/flag state for this launch.
// ---------------------------------------------------------------------------
__global__ __launch_bounds__(512, 1) void kA(
    const float* __restrict__ x,
    const float* __restrict__ Wx, const float* __restrict__ bx,
    const float* __restrict__ Wih, const float* __restrict__ bih,
    const float* __restrict__ bhh)
{
    extern __shared__ float sm[];
    float* sWx   = sm;                    // [64][128]
    float* sWihT = sWx + 64 * 128;        // [128][260]
    float* sbx   = sWihT + 128 * 260;     // [128]
    float* sbU   = sbx + 128;             // [256]
    float* sx    = sbU + 256;             // [64][64]
    float* sfeat = sx + 64 * 64;          // [64][128]

    const int t = threadIdx.x;

    if (blockIdx.x == 0) {                // reset flags/ticket for this launch
        if (t < 128) g_cntH[t] = 0u;
        if (t == 128) g_tick = 0u;
    }

    for (int idx = t; idx < 64 * 128; idx += 512) sWx[idx] = Wx[idx];
    for (int idx = t; idx < 256 * 128; idx += 512) {
        int i = idx >> 7, j = idx & 127;
        sWihT[j * 260 + i] = Wih[idx];
    }
    if (t < 128) sbx[t] = bx[t];
    if (t < 256) sbU[t] = bih[t] + bhh[t];
    __syncthreads();

    const int rg = t >> 6;          // 0..7 -> rows rg*8 + q  (64 rows/tile)
    const int c2 = t & 63;          // phase1 col pair {2c2, 2c2+1}
    const int ii = c2 * 4;          // phase2: 4 consecutive outputs
    const int ntiles = (S_LEN * B_SZ) / 64;

    for (int tile = blockIdx.x; tile < ntiles; tile += gridDim.x) {
        const int row0 = tile * 64;
        { // load 64x64 x tile (contiguous 16KB = 1024 float4)
            const float4* src = (const float4*)(x + (size_t)row0 * XDIM);
            ((float4*)sx)[t]       = src[t];
            ((float4*)sx)[t + 512] = src[t + 512];
        }
        __syncthreads();

        // phase 1: feat = tanh(x @ Wx + bx)   (packed f32x2, 8 rows/thread)
        unsigned long long a[8];
        #pragma unroll
        for (int q = 0; q < 8; q++) a[q] = 0ull;
        #pragma unroll 2
        for (int k4 = 0; k4 < 64; k4 += 4) {
            float xv[8][4];
            #pragma unroll
            for (int q = 0; q < 8; q++)
                *(float4*)&xv[q][0] = *(const float4*)&sx[(rg * 8 + q) * 64 + k4];
            #pragma unroll
            for (int s = 0; s < 4; s++) {
                unsigned long long w =
                    *(const unsigned long long*)&sWx[(k4 + s) * 128 + 2 * c2];
                #pragma unroll
                for (int q = 0; q < 8; q++)
                    a[q] = fma2(pk2(xv[q][s]), w, a[q]);
            }
        }
        {
            const float bx0 = sbx[2 * c2], bx1 = sbx[2 * c2 + 1];
            #pragma unroll
            for (int q = 0; q < 8; q++) {
                const int row = rg * 8 + q;
                sfeat[row * 128 + 2 * c2]     = tanhf(pk_lo(a[q]) + bx0);
                sfeat[row * 128 + 2 * c2 + 1] = tanhf(pk_hi(a[q]) + bx1);
            }
        }
        __syncthreads();

        // phase 2: U = feat @ Wih^T + bias   (packed f32x2, 8 rows/thread)
        unsigned long long acc01[8], acc23[8];
        #pragma unroll
        for (int q = 0; q < 8; q++) { acc01[q] = 0ull; acc23[q] = 0ull; }
        #pragma unroll 2
        for (int j4 = 0; j4 < 128; j4 += 4) {
            float f[8][4];
            #pragma unroll
            for (int q = 0; q < 8; q++)
                *(float4*)&f[q][0] = *(const float4*)&sfeat[(rg * 8 + q) * 128 + j4];
            #pragma unroll
            for (int s = 0; s < 4; s++) {
                ulonglong2 w = *(const ulonglong2*)&sWihT[(j4 + s) * 260 + ii];
                #pragma unroll
                for (int q = 0; q < 8; q++) {
                    unsigned long long fs = pk2(f[q][s]);
                    acc01[q] = fma2(fs, w.x, acc01[q]);
                    acc23[q] = fma2(fs, w.y, acc23[q]);
                }
            }
        }
        float4 bU = *(const float4*)&sbU[ii];
        #pragma unroll
        for (int q = 0; q < 8; q++) {
            float4 o;
            o.x = pk_lo(acc01[q]) + bU.x; o.y = pk_hi(acc01[q]) + bU.y;
            o.z = pk_lo(acc23[q]) + bU.z; o.w = pk_hi(acc23[q]) + bU.w;
            *((float4*)&g_U[(size_t)(row0 + rg * 8 + q) * HDIM + ii]) = o;
        }
        __syncthreads();
    }
}

// ---------------------------------------------------------------------------
// kC tile worker (R14, unchanged): ticket queue + readiness flags.
// ---------------------------------------------------------------------------
__device__ void kc_worker(
    float* sm,
    const float* __restrict__ Whx, const float* __restrict__ bhx,
    const float* __restrict__ Wout, const float* __restrict__ bout,
    float* __restrict__ y)
{
    float* sWhx  = sm;                   // [256][128]
    float* sWout = sWhx + 256 * 128;     // [128][64]
    float* sbhx  = sWout + 128 * 64;     // [128]
    float* sbout = sbhx + 128;           // [64]
    float* sht   = sbout + 64;           // [32][256]
    float* sz    = sht + 32 * 256;       // [32][128]

    __shared__ int s_tile;

    const int t = threadIdx.x;
    for (int idx = t; idx < 256 * 128; idx += 256) sWhx[idx] = Whx[idx];
    for (int idx = t; idx < 128 * 64; idx += 256) sWout[idx] = Wout[idx];
    if (t < 128) sbhx[t] = bhx[t];
    if (t < 64)  sbout[t] = bout[t];
    __syncthreads();

    const int rg  = t >> 5;
    const int jj4 = (t & 31) * 4;
    const int rr  = t >> 4;
    const int oo4 = (t & 15) * 4;

    for (;;) {
        if (t == 0) s_tile = (int)atomicAdd(&g_tick, 1u);
        __syncthreads();
        const int tile = s_tile;
        if (tile >= NTILES_C) break;

        if (t == 0) {                     // wait until g_Hs for this tile is live
            while (ld_acq(&g_cntH[tile >> 5]) < 128u) __nanosleep(256);
        }
        __syncthreads();

        const int row0 = tile * 32;
        {
            const float4* src = (const float4*)(g_Hs + (size_t)row0 * HDIM);
            float4* dst = (float4*)sht;
            #pragma unroll
            for (int q = 0; q < 8; q++) dst[q * 256 + t] = src[q * 256 + t];
        }
        __syncthreads();

        // phase 1: z = tanh(h @ Whx + bhx)
        unsigned long long acc01[4], acc23[4];
        #pragma unroll
        for (int q = 0; q < 4; q++) { acc01[q] = 0ull; acc23[q] = 0ull; }
        #pragma unroll 2
        for (int i4 = 0; i4 < 256; i4 += 4) {
            float hq[4][4];
            #pragma unroll
            for (int q = 0; q < 4; q++)
                *(float4*)&hq[q][0] = *(const float4*)&sht[(rg * 4 + q) * 256 + i4];
            #pragma unroll
            for (int s = 0; s < 4; s++) {
                ulonglong2 w = *(const ulonglong2*)&sWhx[(i4 + s) * 128 + jj4];
                #pragma unroll
                for (int q = 0; q < 4; q++) {
                    unsigned long long hs = pk2(hq[q][s]);
                    acc01[q] = fma2(hs, w.x, acc01[q]);
                    acc23[q] = fma2(hs, w.y, acc23[q]);
                }
            }
        }
        float4 bz = *(const float4*)&sbhx[jj4];
        #pragma unroll
        for (int q = 0; q < 4; q++) {
            const int rw = rg * 4 + q;
            sz[rw * 128 + jj4 + 0] = tanhf(pk_lo(acc01[q]) + bz.x);
            sz[rw * 128 + jj4 + 1] = tanhf(pk_hi(acc01[q]) + bz.y);
            sz[rw * 128 + jj4 + 2] = tanhf(pk_lo(acc23[q]) + bz.z);
            sz[rw * 128 + jj4 + 3] = tanhf(pk_hi(acc23[q]) + bz.w);
        }
        __syncthreads();

        // phase 2: y = z @ Wout + bout
        float4 o[2];
        o[0] = make_float4(0.f, 0.f, 0.f, 0.f);
        o[1] = make_float4(0.f, 0.f, 0.f, 0.f);
        #pragma unroll 2
        for (int j4 = 0; j4 < 128; j4 += 4) {
            float zq[2][4];
            #pragma unroll
            for (int q2 = 0; q2 < 2; q2++)
                *(float4*)&zq[q2][0] = *(const float4*)&sz[(rr * 2 + q2) * 128 + j4];
            #pragma unroll
            for (int s = 0; s < 4; s++) {
                float4 w = *(const float4*)&sWout[(j4 + s) * 64 + oo4];
                #pragma unroll
                for (int q2 = 0; q2 < 2; q2++) {
                    o[q2].x = fmaf(zq[q2][s], w.x, o[q2].x);
                    o[q2].y = fmaf(zq[q2][s], w.y, o[q2].y);
                    o[q2].z = fmaf(zq[q2][s], w.z, o[q2].z);
                    o[q2].w = fmaf(zq[q2][s], w.w, o[q2].w);
                }
            }
        }
        float4 bo = *(const float4*)&sbout[oo4];
        #pragma unroll
        for (int q2 = 0; q2 < 2; q2++) {
            float4 ov;
            ov.x = o[q2].x + bo.x; ov.y = o[q2].y + bo.y;
            ov.z = o[q2].z + bo.z; ov.w = o[q2].w + bo.w;
            *((float4*)&y[(size_t)(row0 + rr * 2 + q2) * ODIM + oo4]) = ov;
        }
        __syncthreads();
    }
}

// ---------------------------------------------------------------------------
// Mega-kernel (R14, unchanged): CTAs 0..127 = kB v4 recurrence with per-16-
// step release flags; CTAs 128..147 = kC workers; recurrence CTAs join the
// worker queue when their loop ends.
// ---------------------------------------------------------------------------
__global__ __launch_bounds__(256, 1) __cluster_dims__(2, 1, 1)
void kBC(const float* __restrict__ Whh, const float* __restrict__ sigmas,
         const float* __restrict__ Whx, const float* __restrict__ bhx,
         const float* __restrict__ Wout, const float* __restrict__ bout,
         float* __restrict__ y)
{
    extern __shared__ float dsm[];              // kC worker storage (dynamic)

    if (blockIdx.x < 128) {
        __shared__ __align__(16) float sh[2][256];
        __shared__ __align__(16) float spart[128];
        __shared__ __align__(8)  unsigned long long mbar[2];

        const int tid   = threadIdx.x;
        const int i_loc = tid & 127;
        const int half  = tid >> 7;
        const uint32_t rank = ctarank();
        const uint32_t peer = rank ^ 1u;
        const int r  = (int)rank;
        const int b  = blockIdx.x >> 1;
        const int gi = r * 128 + i_loc;
        const bool fresh     = (half == r);
        const bool finalizer = (half == 0);
        const int waiter_leader = (r == 0) ? 128 : 0;

        ulonglong2 wreg[32];
        {
            const ulonglong2* ws =
                (const ulonglong2*)(Whh + (size_t)gi * HDIM + 128 * half);
            #pragma unroll
            for (int i = 0; i < 32; i++) wreg[i] = ws[i];
        }

        const float alpha = 1.0f / (1.0f + expf(-sigmas[gi & 3]));
        const float oma   = 1.0f - alpha;

        sh[0][tid] = 0.f;
        sh[1][tid] = 0.f;
        const uint32_t mb[2] = { smem_u32(&mbar[0]), smem_u32(&mbar[1]) };
        const uint32_t sh_a  = smem_u32(&sh[0][0]);
        if (tid == 0) { mbar_init(mb[0], 1); mbar_init(mb[1], 1); }
        __syncthreads();
        if (tid == waiter_leader) {
            mbar_expect_tx(mb[0], 512);
            mbar_expect_tx(mb[1], 512);
        }
        __syncthreads();
        asm volatile("barrier.cluster.arrive.aligned;" ::: "memory");
        asm volatile("barrier.cluster.wait.aligned;" ::: "memory");

        float h_reg  = 0.f;
        float u_next = finalizer ? g_U[(size_t)b * HDIM + gi] : 0.f;

        for (int t = 0; t < S_LEN; t++) {
            const float* hsrc = sh[(t + 1) & 1] + 128 * half;

            if (!fresh && t > 0) {
                const int pm = (t - 1) & 1;
                mbar_wait_cta(mb[pm], (uint32_t)(((t - 1) >> 1) & 1));
                if (tid == waiter_leader)
                    mbar_expect_tx(mb[pm], 512);
            }

            unsigned long long a0 = 0ull, a1 = 0ull, a2 = 0ull, a3 = 0ull;
            #pragma unroll
            for (int i = 0; i < 32; i += 2) {
                ulonglong2 h0 = *(const ulonglong2*)&hsrc[i * 4];
                a0 = fma2(wreg[i].x, h0.x, a0);
                a1 = fma2(wreg[i].y, h0.y, a1);
                ulonglong2 h1 = *(const ulonglong2*)&hsrc[i * 4 + 4];
                a2 = fma2(wreg[i + 1].x, h1.x, a2);
                a3 = fma2(wreg[i + 1].y, h1.y, a3);
            }
            unsigned long long c = add2(add2(a0, a1), add2(a2, a3));
            const float partial = pk_lo(c) + pk_hi(c);

            if (!finalizer) spart[i_loc] = partial;
            __syncthreads();

            if (finalizer) {
                const float u = u_next;
                if (t + 1 < S_LEN)
                    u_next = g_U[((size_t)(t + 1) * B_SZ + b) * HDIM + gi];
                g_Hs[((size_t)t * B_SZ + b) * HDIM + gi] = h_reg;

                const float s  = partial + spart[i_loc] + u;
                const float hn = tanhf(s);
                h_reg = oma * h_reg + alpha * hn;

                const int wb = t & 1;
                sh[wb][gi] = h_reg;
                st_async_peer_f32(sh_a + (uint32_t)((wb * 256 + gi) * 4),
                                  mb[wb], peer, h_reg);
            }
            __syncthreads();

            // publish g_Hs progress every 16 steps (1 thread, off critical path)
            if (((t & 15) == 15) && tid == 0)
                flag_release(&g_cntH[t >> 4]);
        }

        asm volatile("barrier.cluster.arrive.aligned;" ::: "memory");
        asm volatile("barrier.cluster.wait.aligned;" ::: "memory");
    }

    // Everyone (workers from launch; recurrence CTAs afterwards) drains tiles.
    kc_worker(dsm, Whx, bhx, Wout, bout, y);
}

// ---------------------------------------------------------------------------
extern "C" void kernel_launch(void* const* d_in, const int* in_sizes, int n_in,
                              void* d_out, int out_size)
{
    const float* x      = (const float*)d_in[0];
    const float* Wx     = (const float*)d_in[1];
    const float* bx     = (const float*)d_in[2];
    const float* Wih    = (const float*)d_in[3];
    const float* bih    = (const float*)d_in[4];
    const float* Whh    = (const float*)d_in[5];
    const float* bhh    = (const float*)d_in[6];
    const float* Whx    = (const float*)d_in[7];
    const float* bhx    = (const float*)d_in[8];
    const float* Wout   = (const float*)d_in[9];
    const float* bout   = (const float*)d_in[10];
    const float* sigmas = (const float*)d_in[11];
    float* y = (float*)d_out;

    const size_t smA = (size_t)(64*128 + 128*260 + 128 + 256 + 64*64 + 64*128) * 4;
    const size_t smC = (size_t)(256*128 + 128*64 + 128 + 64 + 32*256 + 32*128) * 4;

    cudaFuncSetAttribute(kA, cudaFuncAttributeMaxDynamicSharedMemorySize, (int)smA);
    cudaFuncSetAttribute(kBC, cudaFuncAttributeMaxDynamicSharedMemorySize, (int)smC);

    kA<<<148, 512, smA>>>(x, Wx, bx, Wih, bih, bhh);
    kBC<<<148, 256, smC>>>(Whh, sigmas, Whx, bhx, Wout, bout, y);
}